// round 8
// baseline (speedup 1.0000x reference)
#include <cuda_runtime.h>

// ---------------------------------------------------------------------------
// One fused kernel. 512 threads/block, 4 batch elements per thread (256 blocks
// for B=524288). Per-block setup: coalesced smem staging of weights (issued
// BEFORE the batch loads so staging never queues behind them in L1tex), then
// 2 warps derive the 8 scalar constants. Per-element math is a fully scalar
// inline function — no indexable arrays, no local-memory spills.
// ---------------------------------------------------------------------------

#define P 33                      // padded row stride for Wi in smem
// sV offsets
#define V_QWA 0
#define V_BA  32
#define V_QWB 64
#define V_BB  96
#define V_WF  128
#define V_BOAB 160
#define V_BOBA 192
#define V_BIAB 224
#define V_BIBA 320

// Per-element closed form:
//   S = b0 + db * mean3(sigmoid(fmaf(C0,a_i,C1)*db))
//   T = 0.5 * sum_j softmax3_weighted_mean(a; wj),  wj = fmaf(C4,b_j,C5)
//   y = K0 + C2*S + C6*T ; leaky-relu(0.01)
__device__ __forceinline__ float elem_eval(
    float a0, float a1, float a2, float b0, float b1,
    float C0, float C1, float C2, float C4, float C5, float C6, float K0)
{
    const float db = b1 - b0;
    const float l0 = fmaf(C0, a0, C1) * db;
    const float l1 = fmaf(C0, a1, C1) * db;
    const float l2 = fmaf(C0, a2, C1) * db;
    const float s0 = __fdividef(1.f, 1.f + __expf(-l0));
    const float s1 = __fdividef(1.f, 1.f + __expf(-l1));
    const float s2 = __fdividef(1.f, 1.f + __expf(-l2));
    const float S  = fmaf(db, (s0 + s1 + s2) * (1.f / 3.f), b0);

    // 3-way softmax normalized by the middle exponent (|z| is small: no max).
    const float w0 = fmaf(C4, b0, C5);
    const float u0 = __expf(w0 * (a0 - a1));
    const float v0 = __expf(w0 * (a2 - a1));
    const float t0 = __fdividef(fmaf(a0, u0, fmaf(a2, v0, a1)), u0 + v0 + 1.f);

    const float w1 = fmaf(C4, b1, C5);
    const float u1 = __expf(w1 * (a0 - a1));
    const float v1 = __expf(w1 * (a2 - a1));
    const float t1 = __fdividef(fmaf(a0, u1, fmaf(a2, v1, a1)), u1 + v1 + 1.f);

    const float T = 0.5f * (t0 + t1);
    const float y = fmaf(C2, S, fmaf(C6, T, K0));
    return (y >= 0.f) ? y : 0.01f * y;
}

__global__ void __launch_bounds__(512, 2)
fused_kernel(const float* __restrict__ gA, const float* __restrict__ gB,
             const float* __restrict__ WA, const float* __restrict__ bA,
             const float* __restrict__ WB, const float* __restrict__ bB,
             const float* __restrict__ Wi_AB, const float* __restrict__ bi_AB,
             const float* __restrict__ Wo_AB, const float* __restrict__ bo_AB,
             const float* __restrict__ Wi_BA, const float* __restrict__ bi_BA,
             const float* __restrict__ Wo_BA, const float* __restrict__ bo_BA,
             const float* __restrict__ Wf, const float* __restrict__ bf,
             float* __restrict__ out, int nT, int B)
{
    __shared__ float smWi[2][96 * P];
    __shared__ float smWo[2][32 * 32];
    __shared__ float sV[416];
    __shared__ float sC[9];

    const int tid = threadIdx.x;
    const int t   = blockIdx.x * 512 + tid;     // group of 4 elements
    const bool act = t < nT;

    // ---- phase A: staging loads issued FIRST (they gate the barrier) ----
    {
        const float4* src0 = (const float4*)Wi_AB;
        const float4* src1 = (const float4*)Wi_BA;
        #pragma unroll
        for (int k = tid; k < 768; k += 512) {
            const int r = k >> 3, c = (k & 7) << 2;
            float4 v = src0[k];
            float* d = &smWi[0][r * P + c];
            d[0] = v.x; d[1] = v.y; d[2] = v.z; d[3] = v.w;
            v = src1[k];
            d = &smWi[1][r * P + c];
            d[0] = v.x; d[1] = v.y; d[2] = v.z; d[3] = v.w;
        }
        const int dir = tid >> 8;
        const int k   = tid & 255;
        const float4* src = dir ? (const float4*)Wo_BA : (const float4*)Wo_AB;
        ((float4*)smWo[dir])[k] = src[k];

        if (tid < 32)              sV[V_QWA + tid]        = WA[tid];
        else if (tid < 64)         sV[V_BA  + tid - 32]   = bA[tid - 32];
        else if (tid < 96)         sV[V_QWB + tid - 64]   = WB[tid - 64];
        else if (tid < 128)        sV[V_BB  + tid - 96]   = bB[tid - 96];
        else if (tid < 160)        sV[V_WF  + tid - 128]  = Wf[tid - 128];
        else if (tid < 192)        sV[V_BOAB + tid - 160] = bo_AB[tid - 160];
        else if (tid < 224)        sV[V_BOBA + tid - 192] = bo_BA[tid - 192];
        else if (tid < 320)        sV[V_BIAB + tid - 224] = bi_AB[tid - 224];
        else if (tid < 416)        sV[V_BIBA + tid - 320] = bi_BA[tid - 320];
        else if (tid == 416)       sC[8] = bf[0];
    }

    // ---- batch-data loads (independent; land while setup proceeds) ----
    float4 A0, A1, A2, B0, B1;
    if (act) {
        const float4* gA4 = (const float4*)gA;
        const float4* gB4 = (const float4*)gB;
        A0 = gA4[3 * t]; A1 = gA4[3 * t + 1]; A2 = gA4[3 * t + 2];
        B0 = gB4[2 * t]; B1 = gB4[2 * t + 1];
    }
    __syncthreads();

    // ---- phase B: 2 warps derive the 8 scalar constants ----
    const int warp = tid >> 5;
    const int e    = tid & 31;
    if (warp < 2) {
        const int dir = warp;
        const int qw = dir ? V_QWB : V_QWA;
        const int qb = dir ? V_BB  : V_BA;
        const int kw = dir ? V_QWA : V_QWB;
        const int kb = dir ? V_BA  : V_BB;
        const int bi = dir ? V_BIBA : V_BIAB;
        const int bo = dir ? V_BOBA : V_BOAB;

        const float* rq = &smWi[dir][e * P];
        const float* rk = &smWi[dir][(32 + e) * P];
        const float* rv = &smWi[dir][(64 + e) * P];
        const float* wo = smWo[dir];

        float uq = 0.f, cq = 0.f, uk = 0.f, uv = 0.f, cv = 0.f, g = 0.f;
        #pragma unroll
        for (int d = 0; d < 32; ++d) {
            const float wq = rq[d], wkv = rk[d], wvv = rv[d];
            uq = fmaf(wq,  sV[qw + d], uq);
            cq = fmaf(wq,  sV[qb + d], cq);
            uk = fmaf(wkv, sV[kw + d], uk);
            uv = fmaf(wvv, sV[kw + d], uv);
            cv = fmaf(wvv, sV[kb + d], cv);
            g  = fmaf(sV[V_WF + d], wo[d * 32 + e], g);
        }
        cq += sV[bi + e];
        cv += sV[bi + 64 + e];

        float alpha = uq * uk;
        float gamma = cq * uk;
        float kk    = g * uv;
        float rr    = fmaf(sV[V_WF + e], sV[bo + e], g * cv);
        #pragma unroll
        for (int off = 16; off; off >>= 1) {
            alpha += __shfl_xor_sync(0xffffffffu, alpha, off);
            gamma += __shfl_xor_sync(0xffffffffu, gamma, off);
            kk    += __shfl_xor_sync(0xffffffffu, kk, off);
            rr    += __shfl_xor_sync(0xffffffffu, rr, off);
        }
        if (e == 0) {
            const float inv_sqrtE = 0.17677669529663688f;  // 1/sqrt(32)
            sC[dir * 4 + 0] = alpha * inv_sqrtE;
            sC[dir * 4 + 1] = gamma * inv_sqrtE;
            sC[dir * 4 + 2] = 0.5f * kk;
            sC[dir * 4 + 3] = rr;
        }
    }
    __syncthreads();

    const float C0 = sC[0], C1 = sC[1], C2 = sC[2], C3 = sC[3];
    const float C4 = sC[4], C5 = sC[5], C6 = sC[6], C7 = sC[7];
    const float K0 = fmaf(0.5f, C3 + C7, sC[8]);

    // ---- main compute: 4 elements, fully scalar (no arrays) ----
    if (act) {
        const float r0 = elem_eval(A0.x, A0.y, A0.z, B0.x, B0.y,
                                   C0, C1, C2, C4, C5, C6, K0);
        const float r1 = elem_eval(A0.w, A1.x, A1.y, B0.z, B0.w,
                                   C0, C1, C2, C4, C5, C6, K0);
        const float r2 = elem_eval(A1.z, A1.w, A2.x, B1.x, B1.y,
                                   C0, C1, C2, C4, C5, C6, K0);
        const float r3 = elem_eval(A2.y, A2.z, A2.w, B1.z, B1.w,
                                   C0, C1, C2, C4, C5, C6, K0);
        ((float4*)out)[t] = make_float4(r0, r1, r2, r3);
    }

    // tail for B % 4 != 0 (dead for B = 524288)
    if (blockIdx.x == 0 && tid == 0 && (B & 3)) {
        for (int idx = nT * 4; idx < B; ++idx) {
            const float y = elem_eval(gA[3 * idx], gA[3 * idx + 1], gA[3 * idx + 2],
                                      gB[2 * idx], gB[2 * idx + 1],
                                      C0, C1, C2, C4, C5, C6, K0);
            out[idx] = y;
        }
    }
}

extern "C" void kernel_launch(void* const* d_in, const int* in_sizes, int n_in,
                              void* d_out, int out_size)
{
    const float* gA    = (const float*)d_in[0];   // [B,3]
    const float* gB    = (const float*)d_in[1];   // [B,2]
    const float* WA    = (const float*)d_in[2];   // [32,1]
    const float* bA    = (const float*)d_in[3];   // [32]
    const float* WB    = (const float*)d_in[4];
    const float* bB    = (const float*)d_in[5];
    const float* Wi_AB = (const float*)d_in[6];   // [96,32]
    const float* bi_AB = (const float*)d_in[7];   // [96]
    const float* Wo_AB = (const float*)d_in[8];   // [32,32]
    const float* bo_AB = (const float*)d_in[9];   // [32]
    const float* Wi_BA = (const float*)d_in[10];
    const float* bi_BA = (const float*)d_in[11];
    const float* Wo_BA = (const float*)d_in[12];
    const float* bo_BA = (const float*)d_in[13];
    const float* Wf    = (const float*)d_in[14];  // [1,32]
    const float* bf    = (const float*)d_in[15];  // [1]

    const int B  = in_sizes[0] / 3;
    const int nT = B / 4;                          // groups of 4 elements
    int grid = (nT + 511) / 512;
    if (grid < 1) grid = 1;

    fused_kernel<<<grid, 512>>>(gA, gB, WA, bA, WB, bB,
                                Wi_AB, bi_AB, Wo_AB, bo_AB,
                                Wi_BA, bi_BA, Wo_BA, bo_BA,
                                Wf, bf, (float*)d_out, nT, B);
}